// round 13
// baseline (speedup 1.0000x reference)
#include <cuda_runtime.h>
#include <cuda_fp16.h>
#include <math.h>
#include <stdint.h>

// ---------------- problem constants ----------------
#define BB 2
#define LL 2048
#define DD 256
#define SS 8
#define DEPTH 4
#define VOCAB 32000
#define EE (DD + SS)        // 264
#define ROWS (BB * LL)      // 4096

// ---------------- scratch (device globals; no cudaMalloc allowed) ----------------
__device__ __align__(16) float g_h[ROWS * DD];        // layer activations (ping)
__device__ __align__(16) float g_h2[ROWS * DD];       // layer activations (pong)
__device__ __align__(16) float g_hn[ROWS * DD];       // layernorm output (fp32, for recon)
__device__ __align__(16) __half g_hnh[ROWS * DD];     // layernorm output fp16 (logits A)
__device__ __align__(16) float g_sg[ROWS * 16];       // per-row [state_in(8) | gate_pre(8)]
__device__ __align__(16) float g_states[ROWS * SS];   // scan output states
__device__ __align__(16) float g_wsg[DEPTH * DD * 16];    // [Wi2 | Wi@Wg] per layer
__device__ float g_bsg[DEPTH * 16];
__device__ __align__(16) float g_wcat[DEPTH * EE * DD];   // [Wi1@Wo1 ; Wo2] per layer
__device__ float g_bcat[DEPTH * DD];                      // bi1@Wo1 + bo
__device__ __align__(16) float g_wfold[DEPTH * EE * 16];  // Wcat_i @ Wsg_{i+1}
__device__ float g_bfold[DEPTH * 16];                     // bcat_i@Wsg_{i+1} + bsg_{i+1}
__device__ __align__(16) __half g_wch[(size_t)DD * VOCAB]; // Wc fp16, native [D][V]

// ================= helpers =================
__device__ __forceinline__ uint32_t smem_u32(const void* p) {
    uint32_t a;
    asm("{ .reg .u64 t; cvta.to.shared.u64 t, %1; cvt.u32.u64 %0, t; }" : "=r"(a) : "l"(p));
    return a;
}
__device__ __forceinline__ void cp_async16(uint32_t saddr, const void* gptr) {
    asm volatile("cp.async.cg.shared.global [%0], [%1], 16;" :: "r"(saddr), "l"(gptr));
}
__device__ __forceinline__ void cp_async_commit() {
    asm volatile("cp.async.commit_group;");
}
template<int N>
__device__ __forceinline__ void cp_async_wait() {
    asm volatile("cp.async.wait_group %0;" :: "n"(N) : "memory");
}
__device__ __forceinline__ void mma_f16(float* d, const uint32_t* a, const uint32_t* b) {
    asm volatile(
        "mma.sync.aligned.m16n8k16.row.col.f32.f16.f16.f32 "
        "{%0,%1,%2,%3}, {%4,%5,%6,%7}, {%8,%9}, {%0,%1,%2,%3};"
        : "+f"(d[0]), "+f"(d[1]), "+f"(d[2]), "+f"(d[3])
        : "r"(a[0]), "r"(a[1]), "r"(a[2]), "r"(a[3]), "r"(b[0]), "r"(b[1]));
}
__device__ __forceinline__ void ldsm_x4(uint32_t* r, uint32_t addr) {
    asm volatile("ldmatrix.sync.aligned.m8n8.x4.shared.b16 {%0,%1,%2,%3}, [%4];"
                 : "=r"(r[0]), "=r"(r[1]), "=r"(r[2]), "=r"(r[3]) : "r"(addr));
}
__device__ __forceinline__ void ldsm_x4_t(uint32_t* r, uint32_t addr) {
    asm volatile("ldmatrix.sync.aligned.m8n8.x4.trans.shared.b16 {%0,%1,%2,%3}, [%4];"
                 : "=r"(r[0]), "=r"(r[1]), "=r"(r[2]), "=r"(r[3]) : "r"(addr));
}
#define SW128(x) ((x) ^ (((x) >> 3) & 0x70))

// ---------------- embedding gather ----------------
__global__ void embed_kernel(const int* __restrict__ x, const float* __restrict__ table) {
    int row = blockIdx.x;
    int d = threadIdx.x;
    g_h[row * DD + d] = table[(size_t)x[row] * DD + d];
}

// ---------------- Wc fp32 -> fp16 ----------------
__global__ void convert_wc_kernel(const float* __restrict__ Wc) {
    size_t i = ((size_t)blockIdx.x * 256 + threadIdx.x) * 4;
    float4 v = *(const float4*)(Wc + i);
    __half2* o = (__half2*)(g_wch + i);
    o[0] = __floats2half2_rn(v.x, v.y);
    o[1] = __floats2half2_rn(v.z, v.w);
}

// ---------------- precompute: Wsg = [Wi2 | Wi@Wg], bsg ----------------
__global__ void wf_kernel(const float* __restrict__ Wi, const float* __restrict__ bi,
                          const float* __restrict__ Wg, const float* __restrict__ bg) {
    int i = blockIdx.x;   // layer
    int d = threadIdx.x;  // 0..255
    const float* wi = Wi + (size_t)i * DD * EE;
    const float* wg = Wg + (size_t)i * EE * SS;
    float f[8] = {0.f, 0.f, 0.f, 0.f, 0.f, 0.f, 0.f, 0.f};
    for (int e = 0; e < EE; e++) {
        float a = wi[d * EE + e];
        float4 w0 = *(const float4*)(wg + e * 8);
        float4 w1 = *(const float4*)(wg + e * 8 + 4);
        f[0] += a * w0.x; f[1] += a * w0.y; f[2] += a * w0.z; f[3] += a * w0.w;
        f[4] += a * w1.x; f[5] += a * w1.y; f[6] += a * w1.z; f[7] += a * w1.w;
    }
    float* dst = g_wsg + ((size_t)i * DD + d) * 16;
#pragma unroll
    for (int s = 0; s < 8; s++) dst[s] = wi[d * EE + DD + s];   // Wi2
#pragma unroll
    for (int s = 0; s < 8; s++) dst[8 + s] = f[s];              // Wi@Wg
    if (d < 8) {
        g_bsg[i * 16 + d] = bi[(size_t)i * EE + DD + d];
    } else if (d < 16) {
        int s = d - 8;
        float bv = bg[i * SS + s];
        for (int e = 0; e < EE; e++) bv += bi[(size_t)i * EE + e] * wg[e * 8 + s];
        g_bsg[i * 16 + d] = bv;
    }
}

// ---------------- precompute: Wcat rows 0..255 = Wi1 @ Wo1 ----------------
// grid (32, DEPTH), 256 threads. Block handles 8 d-rows x all 256 n.
__global__ void __launch_bounds__(256)
pregemm_kernel(const float* __restrict__ Wi, const float* __restrict__ Wo) {
    __shared__ float wi_s[8][256];
    const int d0 = blockIdx.x * 8;
    const int L = blockIdx.y;
    const int tid = threadIdx.x;
    const float* wi = Wi + (size_t)L * DD * EE;
    const float* wo = Wo + (size_t)L * EE * DD;

    for (int t = tid; t < 8 * 256; t += 256) {
        int i = t >> 8, e = t & 255;
        wi_s[i][e] = wi[(size_t)(d0 + i) * EE + e];
    }
    __syncthreads();

    float acc[8] = {0.f, 0.f, 0.f, 0.f, 0.f, 0.f, 0.f, 0.f};
    const int n = tid;
    for (int e = 0; e < 256; e++) {
        float b = wo[(size_t)e * DD + n];
#pragma unroll
        for (int i = 0; i < 8; i++) acc[i] += wi_s[i][e] * b;
    }
#pragma unroll
    for (int i = 0; i < 8; i++)
        g_wcat[(size_t)L * EE * DD + (size_t)(d0 + i) * DD + n] = acc[i];
}

// ---------------- precompute: Wcat rows 256..263 (Wo2) + bcat ----------------
__global__ void wcat_tail_kernel(const float* __restrict__ Wo, const float* __restrict__ bi,
                                 const float* __restrict__ bo) {
    int i = blockIdx.x;
    int n = threadIdx.x;  // 0..255
    const float* wo = Wo + (size_t)i * EE * DD;
    float* wc = g_wcat + (size_t)i * EE * DD;
#pragma unroll
    for (int s = 0; s < 8; s++) wc[(DD + s) * DD + n] = wo[(DD + s) * DD + n];
    float bv = bo[(size_t)i * DD + n];
    for (int d = 0; d < DD; d++) bv += bi[(size_t)i * EE + d] * wo[(size_t)d * DD + n];
    g_bcat[(size_t)i * DD + n] = bv;
}

// ---------------- precompute: F_i = Wcat_i @ Wsg_{i+1}, bf_i ----------------
// grid (EE+1, DEPTH-1), 256 threads. Row EE = the bias row (uses bcat_i).
__global__ void wfold_kernel() {
    __shared__ float red[8][16];
    const int r = blockIdx.x;        // 0..264
    const int i = blockIdx.y;        // 0..2
    const int d = threadIdx.x;
    const int lane = d & 31, warp = d >> 5;
    const float* wsg = g_wsg + (size_t)(i + 1) * DD * 16;

    float a = (r < EE) ? g_wcat[(size_t)i * EE * DD + (size_t)r * DD + d]
                       : g_bcat[(size_t)i * DD + d];
    float acc[16];
    const float4* w = (const float4*)(wsg + (size_t)d * 16);
    float4 w0 = w[0], w1 = w[1], w2 = w[2], w3 = w[3];
    acc[0]  = a * w0.x; acc[1]  = a * w0.y; acc[2]  = a * w0.z; acc[3]  = a * w0.w;
    acc[4]  = a * w1.x; acc[5]  = a * w1.y; acc[6]  = a * w1.z; acc[7]  = a * w1.w;
    acc[8]  = a * w2.x; acc[9]  = a * w2.y; acc[10] = a * w2.z; acc[11] = a * w2.w;
    acc[12] = a * w3.x; acc[13] = a * w3.y; acc[14] = a * w3.z; acc[15] = a * w3.w;
#pragma unroll
    for (int c = 0; c < 16; c++)
#pragma unroll
        for (int off = 16; off > 0; off >>= 1)
            acc[c] += __shfl_xor_sync(0xffffffffu, acc[c], off);
    if (lane == 0) {
#pragma unroll
        for (int c = 0; c < 16; c++) red[warp][c] = acc[c];
    }
    __syncthreads();
    if (d < 16) {
        float v = 0.f;
#pragma unroll
        for (int w8 = 0; w8 < 8; w8++) v += red[w8][d];
        if (r < EE) g_wfold[((size_t)i * EE + r) * 16 + d] = v;
        else        g_bfold[i * 16 + d] = v + g_bsg[(i + 1) * 16 + d];
    }
}

// ================= fp32 GEMM, 128x64 tiles, 8x4 microtile, 256 threads =================
// C[M,N'] = A'[M,K] @ [B | F] + [bias | biasF]
//   A' = CONCAT ? [A(256 cols) | S(8 cols)] : A
//   SGMODE: grid.x==5; col blocks 0-3 -> C (256 cols), block 4 -> Csg (16 cols via F)
// Requires M % 128 == 0, K % 8 == 0, ldb/ldc strides float4-aligned.
template<bool CONCAT, bool SGMODE>
__global__ void __launch_bounds__(256)
gemm128_kernel(const float* __restrict__ A, int lda,
               const float* __restrict__ S,
               const float* __restrict__ B, int ldb,
               const float* __restrict__ F,
               const float* __restrict__ bias,
               const float* __restrict__ biasF,
               float* __restrict__ C, int ldc,
               float* __restrict__ Csg,
               int K) {
    __shared__ __align__(16) float As[2][128][12];   // m-major, pitch 12
    __shared__ __align__(16) float Bs[2][8][64];

    const int tid = threadIdx.x;
    const int trow = tid >> 4;          // 0..15
    const int tcol = tid & 15;          // 0..15
    const int row0 = blockIdx.y * 128;
    const int col0 = blockIdx.x * 64;
    const uint32_t sA = smem_u32(As);
    const uint32_t sB = smem_u32(Bs);
    const int nk = K >> 3;

    const int am = tid >> 1;            // 0..127
    const int akc = (tid & 1) * 4;      // 0 or 4

    const bool sgBlock = SGMODE && (col0 >= 256);

    if (sgBlock) {
        for (int t = tid; t < 2 * 8 * 64; t += 256) ((float*)Bs)[t] = 0.f;
        __syncthreads();
    }

    auto load_tile = [&](int kt, int buf) {
        int k0 = kt * 8;
        const float* src;
        if (CONCAT && k0 == DD) src = &S[(size_t)(row0 + am) * 8 + akc];
        else                    src = &A[(size_t)(row0 + am) * lda + k0 + akc];
        cp_async16(sA + (uint32_t)(buf * 6144 + (am * 12 + akc) * 4), src);
        if (tid < 128) {
            int k = tid >> 4;           // 0..7
            int n4 = (tid & 15) * 4;    // 0..60
            if (!sgBlock) {
                cp_async16(sB + (uint32_t)(buf * 2048 + (k * 64 + n4) * 4),
                           &B[(size_t)(k0 + k) * ldb + col0 + n4]);
            } else if (n4 < 16) {
                cp_async16(sB + (uint32_t)(buf * 2048 + (k * 64 + n4) * 4),
                           &F[(size_t)(k0 + k) * 16 + n4]);
            }
        }
        cp_async_commit();
    };

    float acc[8][4];
#pragma unroll
    for (int i = 0; i < 8; i++)
#pragma unroll
        for (int j = 0; j < 4; j++) acc[i][j] = 0.f;

    load_tile(0, 0);

    for (int kt = 0; kt < nk; kt++) {
        if (kt + 1 < nk) {
            load_tile(kt + 1, (kt + 1) & 1);
            cp_async_wait<1>();
        } else {
            cp_async_wait<0>();
        }
        __syncthreads();

        const float (*Ab)[12] = As[kt & 1];
        const float (*Bb)[64] = Bs[kt & 1];
#pragma unroll
        for (int k = 0; k < 8; k++) {
            float rm[8], rn[4];
#pragma unroll
            for (int i = 0; i < 8; i++) rm[i] = Ab[trow * 8 + i][k];
#pragma unroll
            for (int j = 0; j < 4; j++) rn[j] = Bb[k][tcol * 4 + j];
#pragma unroll
            for (int i = 0; i < 8; i++)
#pragma unroll
                for (int j = 0; j < 4; j++) acc[i][j] += rm[i] * rn[j];
        }
        __syncthreads();
    }

    if (!sgBlock) {
        const int c0 = col0 + tcol * 4;
        float bv[4];
#pragma unroll
        for (int j = 0; j < 4; j++) bv[j] = bias ? bias[c0 + j] : 0.f;
#pragma unroll
        for (int i = 0; i < 8; i++) {
            int r = row0 + trow * 8 + i;
            float4 o;
            o.x = acc[i][0] + bv[0];
            o.y = acc[i][1] + bv[1];
            o.z = acc[i][2] + bv[2];
            o.w = acc[i][3] + bv[3];
            *(float4*)(&C[(size_t)r * ldc + c0]) = o;
        }
    } else if (tcol < 4) {
        const int cs = tcol * 4;        // 0..12
        float bv[4];
#pragma unroll
        for (int j = 0; j < 4; j++) bv[j] = biasF[cs + j];
#pragma unroll
        for (int i = 0; i < 8; i++) {
            int r = row0 + trow * 8 + i;
            float4 o;
            o.x = acc[i][0] + bv[0];
            o.y = acc[i][1] + bv[1];
            o.z = acc[i][2] + bv[2];
            o.w = acc[i][3] + bv[3];
            *(float4*)(&Csg[(size_t)r * 16 + cs]) = o;
        }
    }
}

// ---------------- skinny (layer 0 only): g_sg = h @ Wsg0 + bsg0 ----------------
__global__ void skinny_kernel(const float* __restrict__ h, int layer) {
    int warp = threadIdx.x >> 5;
    int lane = threadIdx.x & 31;
    int row = blockIdx.x * 8 + warp;
    const float* wsg = g_wsg + (size_t)layer * DD * 16;

    float acc[16];
#pragma unroll
    for (int c = 0; c < 16; c++) acc[c] = 0.f;

    for (int e = lane; e < DD; e += 32) {
        float a = h[(size_t)row * DD + e];
        const float4* w = (const float4*)(wsg + e * 16);
        float4 w0 = w[0], w1 = w[1], w2 = w[2], w3 = w[3];
        acc[0]  += a * w0.x; acc[1]  += a * w0.y; acc[2]  += a * w0.z; acc[3]  += a * w0.w;
        acc[4]  += a * w1.x; acc[5]  += a * w1.y; acc[6]  += a * w1.z; acc[7]  += a * w1.w;
        acc[8]  += a * w2.x; acc[9]  += a * w2.y; acc[10] += a * w2.z; acc[11] += a * w2.w;
        acc[12] += a * w3.x; acc[13] += a * w3.y; acc[14] += a * w3.z; acc[15] += a * w3.w;
    }
#pragma unroll
    for (int c = 0; c < 16; c++)
#pragma unroll
        for (int off = 16; off > 0; off >>= 1)
            acc[c] += __shfl_xor_sync(0xffffffffu, acc[c], off);

    if (lane < 16) {
        float v = 0.f;
#pragma unroll
        for (int c = 0; c < 16; c++) v = (lane == c) ? acc[c] : v;
        g_sg[(size_t)row * 16 + lane] = v + g_bsg[layer * 16 + lane];
    }
}

// ---------------- scan (sigmoid inside): g_sg -> g_states, finals ----------------
__global__ void scan2_kernel(float* __restrict__ finals, int layer) {
    __shared__ float sA[256];
    __shared__ float sB[256];
    const int b = blockIdx.x >> 3;
    const int s = blockIdx.x & 7;
    const int tid = threadIdx.x;
    constexpr int CH = LL / 256;   // 8

    const int t0 = tid * CH;
    float gl[CH], cl[CH];
    float A = 1.f, Bv = 0.f;
#pragma unroll
    for (int i = 0; i < CH; i++) {
        int row = b * LL + t0 + i;
        float gp = g_sg[(size_t)row * 16 + 8 + s];
        float g = 1.f / (1.f + expf(-gp));
        float si = g_sg[(size_t)row * 16 + s];
        gl[i] = g;
        cl[i] = (1.f - g) * si;
        A  = g * A;
        Bv = g * Bv + cl[i];
    }
    sA[tid] = A; sB[tid] = Bv;
    __syncthreads();

    for (int off = 1; off < 256; off <<= 1) {
        float cA = sA[tid], cB = sB[tid];
        float pA = 1.f, pB = 0.f;
        if (tid >= off) { pA = sA[tid - off]; pB = sB[tid - off]; }
        __syncthreads();
        sA[tid] = cA * pA;
        sB[tid] = cA * pB + cB;
        __syncthreads();
    }

    float st = (tid == 0) ? 0.f : sB[tid - 1];
#pragma unroll
    for (int i = 0; i < CH; i++) {
        int row = b * LL + t0 + i;
        st = gl[i] * st + cl[i];
        g_states[(size_t)row * SS + s] = st;
    }
    if (t0 + CH == LL)
        finals[layer * BB * SS + b * SS + s] = st;
}

// ---------------- layernorm over D=256, one block per row ----------------
__global__ void ln_kernel(const float* __restrict__ gamma, const float* __restrict__ beta) {
    __shared__ float red[8];
    const int row = blockIdx.x;
    const int tid = threadIdx.x;
    const int lane = tid & 31, warp = tid >> 5;

    float x = g_h[(size_t)row * DD + tid];

    float v = x;
#pragma unroll
    for (int off = 16; off > 0; off >>= 1) v += __shfl_xor_sync(0xffffffffu, v, off);
    if (lane == 0) red[warp] = v;
    __syncthreads();
    float tot = 0.f;
#pragma unroll
    for (int i = 0; i < 8; i++) tot += red[i];
    float mu = tot * (1.f / DD);
    float d = x - mu;
    __syncthreads();

    v = d * d;
#pragma unroll
    for (int off = 16; off > 0; off >>= 1) v += __shfl_xor_sync(0xffffffffu, v, off);
    if (lane == 0) red[warp] = v;
    __syncthreads();
    float tot2 = 0.f;
#pragma unroll
    for (int i = 0; i < 8; i++) tot2 += red[i];
    float var = tot2 * (1.f / DD);

    float y = d * rsqrtf(var + 1e-5f) * gamma[tid] + beta[tid];
    g_hn[(size_t)row * DD + tid] = y;
    g_hnh[(size_t)row * DD + tid] = __float2half(y);
}

// ================= fp16 mma.sync logits GEMM (validated round 6) =================
#define GM_M 128
#define GM_N 128
#define GM_KC 64
#define GM_NCHUNK (DD / GM_KC)          // 4
#define ABUF_BYTES (GM_M * GM_KC * 2)   // 16384
#define BBUF_BYTES (GM_KC * GM_N * 2)   // 16384
#define SMEM_BYTES (2 * (ABUF_BYTES + BBUF_BYTES))  // 65536

__global__ void __launch_bounds__(256)
logits_mma_kernel(const float* __restrict__ bc, float* __restrict__ C) {
    extern __shared__ char sm[];
    const int tid = threadIdx.x;
    const int wid = tid >> 5;
    const int lane = tid & 31;
    const int warp_m = wid & 3;
    const int warp_n = wid >> 2;
    const int row0 = blockIdx.y * GM_M;
    const int col0 = blockIdx.x * GM_N;

    const uint32_t s_base = smem_u32(sm);
    const uint32_t aOff[2] = { 0u, (uint32_t)ABUF_BYTES };
    const uint32_t bOff[2] = { (uint32_t)(2 * ABUF_BYTES),
                               (uint32_t)(2 * ABUF_BYTES + BBUF_BYTES) };

    float acc[2][8][4];
#pragma unroll
    for (int mt = 0; mt < 2; mt++)
#pragma unroll
        for (int nt = 0; nt < 8; nt++)
#pragma unroll
            for (int i = 0; i < 4; i++) acc[mt][nt][i] = 0.f;

    auto load_chunk = [&](int c, int buf) {
#pragma unroll
        for (int t = 0; t < 4; t++) {
            int idx = tid + t * 256;
            int m = idx >> 3;
            int c16 = idx & 7;
            cp_async16(s_base + aOff[buf] + (uint32_t)SW128(m * 128 + c16 * 16),
                       &g_hnh[(size_t)(row0 + m) * DD + c * GM_KC + c16 * 8]);
        }
#pragma unroll
        for (int t = 0; t < 4; t++) {
            int idx = tid + t * 256;
            int k = idx >> 4;
            int c16 = idx & 15;
            int group = c16 >> 3;
            int w = (c16 & 7) ^ (k & 7);
            cp_async16(s_base + bOff[buf] + (uint32_t)(k * 256 + group * 128 + w * 16),
                       &g_wch[(size_t)(c * GM_KC + k) * VOCAB + col0 + c16 * 8]);
        }
        cp_async_commit();
    };

    load_chunk(0, 0);

    for (int c = 0; c < GM_NCHUNK; c++) {
        if (c + 1 < GM_NCHUNK) {
            load_chunk(c + 1, (c + 1) & 1);
            cp_async_wait<1>();
        } else {
            cp_async_wait<0>();
        }
        __syncthreads();

        const uint32_t sA = s_base + aOff[c & 1];
        const uint32_t sB = s_base + bOff[c & 1];

#pragma unroll
        for (int ks = 0; ks < GM_KC / 16; ks++) {
            uint32_t afr[2][4];
#pragma unroll
            for (int mt = 0; mt < 2; mt++) {
                int r = warp_m * 32 + mt * 16 + (lane & 15);
                int cb = ks * 32 + (lane >> 4) * 16;
                ldsm_x4(afr[mt], sA + (uint32_t)SW128(r * 128 + cb));
            }
            uint32_t bfr[8][2];
#pragma unroll
            for (int p = 0; p < 4; p++) {
                int k = ks * 16 + ((lane >> 3) & 1) * 8 + (lane & 7);
                int n = warp_n * 64 + p * 16 + (lane >> 4) * 8;
                int c16 = n >> 3;
                int group = c16 >> 3;
                int w = (c16 & 7) ^ (k & 7);
                uint32_t tmp[4];
                ldsm_x4_t(tmp, sB + (uint32_t)(k * 256 + group * 128 + w * 16));
                bfr[p * 2 + 0][0] = tmp[0]; bfr[p * 2 + 0][1] = tmp[1];
                bfr[p * 2 + 1][0] = tmp[2]; bfr[p * 2 + 1][1] = tmp[3];
            }
#pragma unroll
            for (int mt = 0; mt < 2; mt++)
#pragma unroll
                for (int nt = 0; nt < 8; nt++)
                    mma_f16(acc[mt][nt], afr[mt], bfr[nt]);
        }
        __syncthreads();
    }

#pragma unroll
    for (int nt = 0; nt < 8; nt++) {
        int cc = col0 + warp_n * 64 + nt * 8 + (lane & 3) * 2;
        float2 bv = *(const float2*)(&bc[cc]);
#pragma unroll
        for (int mt = 0; mt < 2; mt++) {
            int r = row0 + warp_m * 32 + mt * 16 + (lane >> 2);
            float2 v0 = make_float2(acc[mt][nt][0] + bv.x, acc[mt][nt][1] + bv.y);
            float2 v1 = make_float2(acc[mt][nt][2] + bv.x, acc[mt][nt][3] + bv.y);
            *(float2*)(&C[(size_t)r * VOCAB + cc]) = v0;
            *(float2*)(&C[(size_t)(r + 8) * VOCAB + cc]) = v1;
        }
    }
}

// ---------------- launch ----------------
extern "C" void kernel_launch(void* const* d_in, const int* in_sizes, int n_in,
                              void* d_out, int out_size) {
    const int*   x_t   = (const int*)  d_in[0];
    const float* table = (const float*)d_in[1];
    const float* Wi    = (const float*)d_in[2];
    const float* bi    = (const float*)d_in[3];
    const float* Wg    = (const float*)d_in[4];
    const float* bg    = (const float*)d_in[5];
    const float* Wo    = (const float*)d_in[6];
    const float* bo    = (const float*)d_in[7];
    const float* gamma = (const float*)d_in[8];
    const float* beta  = (const float*)d_in[9];
    const float* Wc    = (const float*)d_in[10];
    const float* bc    = (const float*)d_in[11];
    const float* Wr    = (const float*)d_in[12];
    const float* br    = (const float*)d_in[13];

    float* out    = (float*)d_out;
    float* logits = out;
    float* recon  = out + (size_t)ROWS * VOCAB;
    float* finals = recon + (size_t)ROWS * DD;

    float *h_p = nullptr, *h2_p = nullptr, *hn_p = nullptr;
    float *states_p = nullptr, *wcat_p = nullptr, *bcat_p = nullptr;
    float *wfold_p = nullptr, *bfold_p = nullptr, *sg_p = nullptr;
    cudaGetSymbolAddress((void**)&h_p,      g_h);
    cudaGetSymbolAddress((void**)&h2_p,     g_h2);
    cudaGetSymbolAddress((void**)&hn_p,     g_hn);
    cudaGetSymbolAddress((void**)&states_p, g_states);
    cudaGetSymbolAddress((void**)&wcat_p,   g_wcat);
    cudaGetSymbolAddress((void**)&bcat_p,   g_bcat);
    cudaGetSymbolAddress((void**)&wfold_p,  g_wfold);
    cudaGetSymbolAddress((void**)&bfold_p,  g_bfold);
    cudaGetSymbolAddress((void**)&sg_p,     g_sg);

    cudaFuncSetAttribute(logits_mma_kernel,
                         cudaFuncAttributeMaxDynamicSharedMemorySize, SMEM_BYTES);

    // ---- inputs / precompute ----
    embed_kernel<<<ROWS, DD>>>(x_t, table);
    convert_wc_kernel<<<(DD * VOCAB) / 1024, 256>>>(Wc);
    wf_kernel<<<DEPTH, DD>>>(Wi, bi, Wg, bg);
    pregemm_kernel<<<dim3(32, DEPTH), 256>>>(Wi, Wo);       // Wcat rows 0..255
    wcat_tail_kernel<<<DEPTH, DD>>>(Wo, bi, bo);            // rows 256..263 + bcat
    wfold_kernel<<<dim3(EE + 1, DEPTH - 1), 256>>>();       // F_i, bf_i (i=0..2)

    // ---- layers ----
    skinny_kernel<<<ROWS / 8, 256>>>(h_p, 0);               // sg_0 from embed h
    for (int i = 0; i < DEPTH; i++) {
        const float* hin  = (i & 1) ? h2_p : h_p;
        float*       hout = (i & 1) ? h_p  : h2_p;
        scan2_kernel<<<BB * SS, 256>>>(finals, i);
        if (i < DEPTH - 1) {
            gemm128_kernel<true, true><<<dim3(5, ROWS / 128), 256>>>(
                hin, DD, states_p,
                wcat_p + (size_t)i * EE * DD, DD,
                wfold_p + (size_t)i * EE * 16,
                bcat_p + (size_t)i * DD,
                bfold_p + (size_t)i * 16,
                hout, DD, sg_p, EE);
        } else {
            gemm128_kernel<true, false><<<dim3(4, ROWS / 128), 256>>>(
                hin, DD, states_p,
                wcat_p + (size_t)i * EE * DD, DD,
                nullptr,
                bcat_p + (size_t)i * DD,
                nullptr,
                hout, DD, nullptr, EE);
        }
    }

    ln_kernel<<<ROWS, DD>>>(gamma, beta);

    // logits via fp16 mma.sync
    logits_mma_kernel<<<dim3(VOCAB / GM_N, ROWS / GM_M), 256, SMEM_BYTES>>>(bc, logits);

    // recon = hn @ Wr + br (fp32)
    gemm128_kernel<false, false><<<dim3(4, ROWS / 128), 256>>>(
        hn_p, DD, nullptr, Wr, DD, nullptr, br, nullptr, recon, DD, nullptr, DD);
}

// round 17
// speedup vs baseline: 1.0274x; 1.0274x over previous
#include <cuda_runtime.h>
#include <cuda_fp16.h>
#include <math.h>
#include <stdint.h>

// ---------------- problem constants ----------------
#define BB 2
#define LL 2048
#define DD 256
#define SS 8
#define DEPTH 4
#define VOCAB 32000
#define EE (DD + SS)        // 264
#define ROWS (BB * LL)      // 4096

// ---------------- scratch (device globals; no cudaMalloc allowed) ----------------
__device__ __align__(16) float g_h[ROWS * DD];        // layer activations (ping)
__device__ __align__(16) float g_h2[ROWS * DD];       // layer activations (pong)
__device__ __align__(16) float g_hn[ROWS * DD];       // layernorm output (fp32, for recon)
__device__ __align__(16) __half g_hnh[ROWS * DD];     // layernorm output fp16 (logits A)
__device__ __align__(16) float g_sg[ROWS * 16];       // per-row [state_in(8) | gate_pre(8)]
__device__ __align__(16) float g_states[ROWS * SS];   // scan output states
__device__ __align__(16) float g_wsg[DEPTH * DD * 16];    // [Wi2 | Wi@Wg] per layer
__device__ float g_bsg[DEPTH * 16];
__device__ __align__(16) float g_wcat[DEPTH * EE * DD];   // [Wi1@Wo1 ; Wo2] per layer
__device__ float g_bcat[DEPTH * DD];                      // bi1@Wo1 + bo
__device__ __align__(16) float g_wfold[DEPTH * EE * 16];  // Wcat_i @ Wsg_{i+1}
__device__ float g_bfold[DEPTH * 16];                     // bcat_i@Wsg_{i+1} + bsg_{i+1}
__device__ __align__(16) __half g_wch[(size_t)DD * VOCAB]; // Wc fp16, native [D][V]

// ================= helpers =================
__device__ __forceinline__ uint32_t smem_u32(const void* p) {
    uint32_t a;
    asm("{ .reg .u64 t; cvta.to.shared.u64 t, %1; cvt.u32.u64 %0, t; }" : "=r"(a) : "l"(p));
    return a;
}
__device__ __forceinline__ void cp_async16(uint32_t saddr, const void* gptr) {
    asm volatile("cp.async.cg.shared.global [%0], [%1], 16;" :: "r"(saddr), "l"(gptr));
}
__device__ __forceinline__ void cp_async_commit() {
    asm volatile("cp.async.commit_group;");
}
template<int N>
__device__ __forceinline__ void cp_async_wait() {
    asm volatile("cp.async.wait_group %0;" :: "n"(N) : "memory");
}
__device__ __forceinline__ void mma_f16(float* d, const uint32_t* a, const uint32_t* b) {
    asm volatile(
        "mma.sync.aligned.m16n8k16.row.col.f32.f16.f16.f32 "
        "{%0,%1,%2,%3}, {%4,%5,%6,%7}, {%8,%9}, {%0,%1,%2,%3};"
        : "+f"(d[0]), "+f"(d[1]), "+f"(d[2]), "+f"(d[3])
        : "r"(a[0]), "r"(a[1]), "r"(a[2]), "r"(a[3]), "r"(b[0]), "r"(b[1]));
}
__device__ __forceinline__ void ldsm_x4(uint32_t* r, uint32_t addr) {
    asm volatile("ldmatrix.sync.aligned.m8n8.x4.shared.b16 {%0,%1,%2,%3}, [%4];"
                 : "=r"(r[0]), "=r"(r[1]), "=r"(r[2]), "=r"(r[3]) : "r"(addr));
}
__device__ __forceinline__ void ldsm_x4_t(uint32_t* r, uint32_t addr) {
    asm volatile("ldmatrix.sync.aligned.m8n8.x4.trans.shared.b16 {%0,%1,%2,%3}, [%4];"
                 : "=r"(r[0]), "=r"(r[1]), "=r"(r[2]), "=r"(r[3]) : "r"(addr));
}
#define SW128(x) ((x) ^ (((x) >> 3) & 0x70))

// ---------------- embedding gather ----------------
__global__ void embed_kernel(const int* __restrict__ x, const float* __restrict__ table) {
    int row = blockIdx.x;
    int d = threadIdx.x;
    g_h[row * DD + d] = table[(size_t)x[row] * DD + d];
}

// ---------------- Wc fp32 -> fp16 ----------------
__global__ void convert_wc_kernel(const float* __restrict__ Wc) {
    size_t i = ((size_t)blockIdx.x * 256 + threadIdx.x) * 4;
    float4 v = *(const float4*)(Wc + i);
    __half2* o = (__half2*)(g_wch + i);
    o[0] = __floats2half2_rn(v.x, v.y);
    o[1] = __floats2half2_rn(v.z, v.w);
}

// ---------------- precompute: Wsg = [Wi2 | Wi@Wg], bsg ----------------
__global__ void wf_kernel(const float* __restrict__ Wi, const float* __restrict__ bi,
                          const float* __restrict__ Wg, const float* __restrict__ bg) {
    int i = blockIdx.x;   // layer
    int d = threadIdx.x;  // 0..255
    const float* wi = Wi + (size_t)i * DD * EE;
    const float* wg = Wg + (size_t)i * EE * SS;
    float f[8] = {0.f, 0.f, 0.f, 0.f, 0.f, 0.f, 0.f, 0.f};
    for (int e = 0; e < EE; e++) {
        float a = wi[d * EE + e];
        float4 w0 = *(const float4*)(wg + e * 8);
        float4 w1 = *(const float4*)(wg + e * 8 + 4);
        f[0] += a * w0.x; f[1] += a * w0.y; f[2] += a * w0.z; f[3] += a * w0.w;
        f[4] += a * w1.x; f[5] += a * w1.y; f[6] += a * w1.z; f[7] += a * w1.w;
    }
    float* dst = g_wsg + ((size_t)i * DD + d) * 16;
#pragma unroll
    for (int s = 0; s < 8; s++) dst[s] = wi[d * EE + DD + s];   // Wi2
#pragma unroll
    for (int s = 0; s < 8; s++) dst[8 + s] = f[s];              // Wi@Wg
    if (d < 8) {
        g_bsg[i * 16 + d] = bi[(size_t)i * EE + DD + d];
    } else if (d < 16) {
        int s = d - 8;
        float bv = bg[i * SS + s];
        for (int e = 0; e < EE; e++) bv += bi[(size_t)i * EE + e] * wg[e * 8 + s];
        g_bsg[i * 16 + d] = bv;
    }
}

// ---------------- precompute: Wcat rows 256..263 (Wo2) + bcat ----------------
__global__ void wcat_tail_kernel(const float* __restrict__ Wo, const float* __restrict__ bi,
                                 const float* __restrict__ bo) {
    int i = blockIdx.x;
    int n = threadIdx.x;  // 0..255
    const float* wo = Wo + (size_t)i * EE * DD;
    float* wc = g_wcat + (size_t)i * EE * DD;
#pragma unroll
    for (int s = 0; s < 8; s++) wc[(DD + s) * DD + n] = wo[(DD + s) * DD + n];
    float bv = bo[(size_t)i * DD + n];
    for (int d = 0; d < DD; d++) bv += bi[(size_t)i * EE + d] * wo[(size_t)d * DD + n];
    g_bcat[(size_t)i * DD + n] = bv;
}

// ---------------- precompute: F_i = Wcat_i @ Wsg_{i+1}, bf_i ----------------
// grid (EE+1, DEPTH-1), 256 threads. Row EE = the bias row (uses bcat_i).
__global__ void wfold_kernel() {
    __shared__ float red[8][16];
    const int r = blockIdx.x;        // 0..264
    const int i = blockIdx.y;        // 0..2
    const int d = threadIdx.x;
    const int lane = d & 31, warp = d >> 5;
    const float* wsg = g_wsg + (size_t)(i + 1) * DD * 16;

    float a = (r < EE) ? g_wcat[(size_t)i * EE * DD + (size_t)r * DD + d]
                       : g_bcat[(size_t)i * DD + d];
    float acc[16];
    const float4* w = (const float4*)(wsg + (size_t)d * 16);
    float4 w0 = w[0], w1 = w[1], w2 = w[2], w3 = w[3];
    acc[0]  = a * w0.x; acc[1]  = a * w0.y; acc[2]  = a * w0.z; acc[3]  = a * w0.w;
    acc[4]  = a * w1.x; acc[5]  = a * w1.y; acc[6]  = a * w1.z; acc[7]  = a * w1.w;
    acc[8]  = a * w2.x; acc[9]  = a * w2.y; acc[10] = a * w2.z; acc[11] = a * w2.w;
    acc[12] = a * w3.x; acc[13] = a * w3.y; acc[14] = a * w3.z; acc[15] = a * w3.w;
#pragma unroll
    for (int c = 0; c < 16; c++)
#pragma unroll
        for (int off = 16; off > 0; off >>= 1)
            acc[c] += __shfl_xor_sync(0xffffffffu, acc[c], off);
    if (lane == 0) {
#pragma unroll
        for (int c = 0; c < 16; c++) red[warp][c] = acc[c];
    }
    __syncthreads();
    if (d < 16) {
        float v = 0.f;
#pragma unroll
        for (int w8 = 0; w8 < 8; w8++) v += red[w8][d];
        if (r < EE) g_wfold[((size_t)i * EE + r) * 16 + d] = v;
        else        g_bfold[i * 16 + d] = v + g_bsg[(i + 1) * 16 + d];
    }
}

// ================= fp32 GEMM, 128x64 tiles, 8x4 microtile, 256 threads =================
// C[M,N'] = A'[M,K] @ [B | F] + [bias | biasF]
//   A' = CONCAT ? [A(256 cols) | S(8 cols)] : A
//   SGMODE: grid.x==5; col blocks 0-3 -> C (256 cols), block 4 -> Csg (16 cols via F)
// z-batched via aStride/bStride/cStride (pass 0 and gridDim.z=1 for unbatched).
// Requires M % 128 == 0, K % 8 == 0, ldb/ldc strides float4-aligned.
template<bool CONCAT, bool SGMODE>
__global__ void __launch_bounds__(256)
gemm128_kernel(const float* __restrict__ A, int lda, size_t aStride,
               const float* __restrict__ S,
               const float* __restrict__ B, int ldb, size_t bStride,
               const float* __restrict__ F,
               const float* __restrict__ bias,
               const float* __restrict__ biasF,
               float* __restrict__ C, int ldc, size_t cStride,
               float* __restrict__ Csg,
               int K) {
    __shared__ __align__(16) float As[2][128][12];   // m-major, pitch 12
    __shared__ __align__(16) float Bs[2][8][64];

    A += (size_t)blockIdx.z * aStride;
    B += (size_t)blockIdx.z * bStride;
    C += (size_t)blockIdx.z * cStride;

    const int tid = threadIdx.x;
    const int trow = tid >> 4;          // 0..15
    const int tcol = tid & 15;          // 0..15
    const int row0 = blockIdx.y * 128;
    const int col0 = blockIdx.x * 64;
    const uint32_t sA = smem_u32(As);
    const uint32_t sB = smem_u32(Bs);
    const int nk = K >> 3;

    const int am = tid >> 1;            // 0..127
    const int akc = (tid & 1) * 4;      // 0 or 4

    const bool sgBlock = SGMODE && (col0 >= 256);

    if (sgBlock) {
        for (int t = tid; t < 2 * 8 * 64; t += 256) ((float*)Bs)[t] = 0.f;
        __syncthreads();
    }

    auto load_tile = [&](int kt, int buf) {
        int k0 = kt * 8;
        const float* src;
        if (CONCAT && k0 == DD) src = &S[(size_t)(row0 + am) * 8 + akc];
        else                    src = &A[(size_t)(row0 + am) * lda + k0 + akc];
        cp_async16(sA + (uint32_t)(buf * 6144 + (am * 12 + akc) * 4), src);
        if (tid < 128) {
            int k = tid >> 4;           // 0..7
            int n4 = (tid & 15) * 4;    // 0..60
            if (!sgBlock) {
                cp_async16(sB + (uint32_t)(buf * 2048 + (k * 64 + n4) * 4),
                           &B[(size_t)(k0 + k) * ldb + col0 + n4]);
            } else if (n4 < 16) {
                cp_async16(sB + (uint32_t)(buf * 2048 + (k * 64 + n4) * 4),
                           &F[(size_t)(k0 + k) * 16 + n4]);
            }
        }
        cp_async_commit();
    };

    float acc[8][4];
#pragma unroll
    for (int i = 0; i < 8; i++)
#pragma unroll
        for (int j = 0; j < 4; j++) acc[i][j] = 0.f;

    load_tile(0, 0);

    for (int kt = 0; kt < nk; kt++) {
        if (kt + 1 < nk) {
            load_tile(kt + 1, (kt + 1) & 1);
            cp_async_wait<1>();
        } else {
            cp_async_wait<0>();
        }
        __syncthreads();

        const float (*Ab)[12] = As[kt & 1];
        const float (*Bb)[64] = Bs[kt & 1];
#pragma unroll
        for (int k = 0; k < 8; k++) {
            float rm[8], rn[4];
#pragma unroll
            for (int i = 0; i < 8; i++) rm[i] = Ab[trow * 8 + i][k];
#pragma unroll
            for (int j = 0; j < 4; j++) rn[j] = Bb[k][tcol * 4 + j];
#pragma unroll
            for (int i = 0; i < 8; i++)
#pragma unroll
                for (int j = 0; j < 4; j++) acc[i][j] += rm[i] * rn[j];
        }
        __syncthreads();
    }

    if (!sgBlock) {
        const int c0 = col0 + tcol * 4;
        float bv[4];
#pragma unroll
        for (int j = 0; j < 4; j++) bv[j] = bias ? bias[c0 + j] : 0.f;
#pragma unroll
        for (int i = 0; i < 8; i++) {
            int r = row0 + trow * 8 + i;
            float4 o;
            o.x = acc[i][0] + bv[0];
            o.y = acc[i][1] + bv[1];
            o.z = acc[i][2] + bv[2];
            o.w = acc[i][3] + bv[3];
            *(float4*)(&C[(size_t)r * ldc + c0]) = o;
        }
    } else if (tcol < 4) {
        const int cs = tcol * 4;        // 0..12
        float bv[4];
#pragma unroll
        for (int j = 0; j < 4; j++) bv[j] = biasF[cs + j];
#pragma unroll
        for (int i = 0; i < 8; i++) {
            int r = row0 + trow * 8 + i;
            float4 o;
            o.x = acc[i][0] + bv[0];
            o.y = acc[i][1] + bv[1];
            o.z = acc[i][2] + bv[2];
            o.w = acc[i][3] + bv[3];
            *(float4*)(&Csg[(size_t)r * 16 + cs]) = o;
        }
    }
}

// ---------------- skinny (layer 0 only): g_sg = h @ Wsg0 + bsg0 ----------------
__global__ void skinny_kernel(const float* __restrict__ h, int layer) {
    int warp = threadIdx.x >> 5;
    int lane = threadIdx.x & 31;
    int row = blockIdx.x * 8 + warp;
    const float* wsg = g_wsg + (size_t)layer * DD * 16;

    float acc[16];
#pragma unroll
    for (int c = 0; c < 16; c++) acc[c] = 0.f;

    for (int e = lane; e < DD; e += 32) {
        float a = h[(size_t)row * DD + e];
        const float4* w = (const float4*)(wsg + e * 16);
        float4 w0 = w[0], w1 = w[1], w2 = w[2], w3 = w[3];
        acc[0]  += a * w0.x; acc[1]  += a * w0.y; acc[2]  += a * w0.z; acc[3]  += a * w0.w;
        acc[4]  += a * w1.x; acc[5]  += a * w1.y; acc[6]  += a * w1.z; acc[7]  += a * w1.w;
        acc[8]  += a * w2.x; acc[9]  += a * w2.y; acc[10] += a * w2.z; acc[11] += a * w2.w;
        acc[12] += a * w3.x; acc[13] += a * w3.y; acc[14] += a * w3.z; acc[15] += a * w3.w;
    }
#pragma unroll
    for (int c = 0; c < 16; c++)
#pragma unroll
        for (int off = 16; off > 0; off >>= 1)
            acc[c] += __shfl_xor_sync(0xffffffffu, acc[c], off);

    if (lane < 16) {
        float v = 0.f;
#pragma unroll
        for (int c = 0; c < 16; c++) v = (lane == c) ? acc[c] : v;
        g_sg[(size_t)row * 16 + lane] = v + g_bsg[layer * 16 + lane];
    }
}

// ---------------- scan (sigmoid inside): g_sg -> g_states, finals ----------------
__global__ void scan2_kernel(float* __restrict__ finals, int layer) {
    __shared__ float sA[256];
    __shared__ float sB[256];
    const int b = blockIdx.x >> 3;
    const int s = blockIdx.x & 7;
    const int tid = threadIdx.x;
    constexpr int CH = LL / 256;   // 8

    const int t0 = tid * CH;
    float gl[CH], cl[CH];
    float A = 1.f, Bv = 0.f;
#pragma unroll
    for (int i = 0; i < CH; i++) {
        int row = b * LL + t0 + i;
        float gp = g_sg[(size_t)row * 16 + 8 + s];
        float g = 1.f / (1.f + expf(-gp));
        float si = g_sg[(size_t)row * 16 + s];
        gl[i] = g;
        cl[i] = (1.f - g) * si;
        A  = g * A;
        Bv = g * Bv + cl[i];
    }
    sA[tid] = A; sB[tid] = Bv;
    __syncthreads();

    for (int off = 1; off < 256; off <<= 1) {
        float cA = sA[tid], cB = sB[tid];
        float pA = 1.f, pB = 0.f;
        if (tid >= off) { pA = sA[tid - off]; pB = sB[tid - off]; }
        __syncthreads();
        sA[tid] = cA * pA;
        sB[tid] = cA * pB + cB;
        __syncthreads();
    }

    float st = (tid == 0) ? 0.f : sB[tid - 1];
#pragma unroll
    for (int i = 0; i < CH; i++) {
        int row = b * LL + t0 + i;
        st = gl[i] * st + cl[i];
        g_states[(size_t)row * SS + s] = st;
    }
    if (t0 + CH == LL)
        finals[layer * BB * SS + b * SS + s] = st;
}

// ---------------- layernorm over D=256, one block per row ----------------
__global__ void ln_kernel(const float* __restrict__ gamma, const float* __restrict__ beta) {
    __shared__ float red[8];
    const int row = blockIdx.x;
    const int tid = threadIdx.x;
    const int lane = tid & 31, warp = tid >> 5;

    float x = g_h[(size_t)row * DD + tid];

    float v = x;
#pragma unroll
    for (int off = 16; off > 0; off >>= 1) v += __shfl_xor_sync(0xffffffffu, v, off);
    if (lane == 0) red[warp] = v;
    __syncthreads();
    float tot = 0.f;
#pragma unroll
    for (int i = 0; i < 8; i++) tot += red[i];
    float mu = tot * (1.f / DD);
    float d = x - mu;
    __syncthreads();

    v = d * d;
#pragma unroll
    for (int off = 16; off > 0; off >>= 1) v += __shfl_xor_sync(0xffffffffu, v, off);
    if (lane == 0) red[warp] = v;
    __syncthreads();
    float tot2 = 0.f;
#pragma unroll
    for (int i = 0; i < 8; i++) tot2 += red[i];
    float var = tot2 * (1.f / DD);

    float y = d * rsqrtf(var + 1e-5f) * gamma[tid] + beta[tid];
    g_hn[(size_t)row * DD + tid] = y;
    g_hnh[(size_t)row * DD + tid] = __float2half(y);
}

// ================= fp16 mma.sync logits GEMM (validated round 6) =================
#define GM_M 128
#define GM_N 128
#define GM_KC 64
#define GM_NCHUNK (DD / GM_KC)          // 4
#define ABUF_BYTES (GM_M * GM_KC * 2)   // 16384
#define BBUF_BYTES (GM_KC * GM_N * 2)   // 16384
#define SMEM_BYTES (2 * (ABUF_BYTES + BBUF_BYTES))  // 65536

__global__ void __launch_bounds__(256)
logits_mma_kernel(const float* __restrict__ bc, float* __restrict__ C) {
    extern __shared__ char sm[];
    const int tid = threadIdx.x;
    const int wid = tid >> 5;
    const int lane = tid & 31;
    const int warp_m = wid & 3;
    const int warp_n = wid >> 2;
    const int row0 = blockIdx.y * GM_M;
    const int col0 = blockIdx.x * GM_N;

    const uint32_t s_base = smem_u32(sm);
    const uint32_t aOff[2] = { 0u, (uint32_t)ABUF_BYTES };
    const uint32_t bOff[2] = { (uint32_t)(2 * ABUF_BYTES),
                               (uint32_t)(2 * ABUF_BYTES + BBUF_BYTES) };

    float acc[2][8][4];
#pragma unroll
    for (int mt = 0; mt < 2; mt++)
#pragma unroll
        for (int nt = 0; nt < 8; nt++)
#pragma unroll
            for (int i = 0; i < 4; i++) acc[mt][nt][i] = 0.f;

    auto load_chunk = [&](int c, int buf) {
#pragma unroll
        for (int t = 0; t < 4; t++) {
            int idx = tid + t * 256;
            int m = idx >> 3;
            int c16 = idx & 7;
            cp_async16(s_base + aOff[buf] + (uint32_t)SW128(m * 128 + c16 * 16),
                       &g_hnh[(size_t)(row0 + m) * DD + c * GM_KC + c16 * 8]);
        }
#pragma unroll
        for (int t = 0; t < 4; t++) {
            int idx = tid + t * 256;
            int k = idx >> 4;
            int c16 = idx & 15;
            int group = c16 >> 3;
            int w = (c16 & 7) ^ (k & 7);
            cp_async16(s_base + bOff[buf] + (uint32_t)(k * 256 + group * 128 + w * 16),
                       &g_wch[(size_t)(c * GM_KC + k) * VOCAB + col0 + c16 * 8]);
        }
        cp_async_commit();
    };

    load_chunk(0, 0);

    for (int c = 0; c < GM_NCHUNK; c++) {
        if (c + 1 < GM_NCHUNK) {
            load_chunk(c + 1, (c + 1) & 1);
            cp_async_wait<1>();
        } else {
            cp_async_wait<0>();
        }
        __syncthreads();

        const uint32_t sA = s_base + aOff[c & 1];
        const uint32_t sB = s_base + bOff[c & 1];

#pragma unroll
        for (int ks = 0; ks < GM_KC / 16; ks++) {
            uint32_t afr[2][4];
#pragma unroll
            for (int mt = 0; mt < 2; mt++) {
                int r = warp_m * 32 + mt * 16 + (lane & 15);
                int cb = ks * 32 + (lane >> 4) * 16;
                ldsm_x4(afr[mt], sA + (uint32_t)SW128(r * 128 + cb));
            }
            uint32_t bfr[8][2];
#pragma unroll
            for (int p = 0; p < 4; p++) {
                int k = ks * 16 + ((lane >> 3) & 1) * 8 + (lane & 7);
                int n = warp_n * 64 + p * 16 + (lane >> 4) * 8;
                int c16 = n >> 3;
                int group = c16 >> 3;
                int w = (c16 & 7) ^ (k & 7);
                uint32_t tmp[4];
                ldsm_x4_t(tmp, sB + (uint32_t)(k * 256 + group * 128 + w * 16));
                bfr[p * 2 + 0][0] = tmp[0]; bfr[p * 2 + 0][1] = tmp[1];
                bfr[p * 2 + 1][0] = tmp[2]; bfr[p * 2 + 1][1] = tmp[3];
            }
#pragma unroll
            for (int mt = 0; mt < 2; mt++)
#pragma unroll
                for (int nt = 0; nt < 8; nt++)
                    mma_f16(acc[mt][nt], afr[mt], bfr[nt]);
        }
        __syncthreads();
    }

#pragma unroll
    for (int nt = 0; nt < 8; nt++) {
        int cc = col0 + warp_n * 64 + nt * 8 + (lane & 3) * 2;
        float2 bv = *(const float2*)(&bc[cc]);
#pragma unroll
        for (int mt = 0; mt < 2; mt++) {
            int r = row0 + warp_m * 32 + mt * 16 + (lane >> 2);
            float2 v0 = make_float2(acc[mt][nt][0] + bv.x, acc[mt][nt][1] + bv.y);
            float2 v1 = make_float2(acc[mt][nt][2] + bv.x, acc[mt][nt][3] + bv.y);
            *(float2*)(&C[(size_t)r * VOCAB + cc]) = v0;
            *(float2*)(&C[(size_t)(r + 8) * VOCAB + cc]) = v1;
        }
    }
}

// ---------------- launch ----------------
extern "C" void kernel_launch(void* const* d_in, const int* in_sizes, int n_in,
                              void* d_out, int out_size) {
    const int*   x_t   = (const int*)  d_in[0];
    const float* table = (const float*)d_in[1];
    const float* Wi    = (const float*)d_in[2];
    const float* bi    = (const float*)d_in[3];
    const float* Wg    = (const float*)d_in[4];
    const float* bg    = (const float*)d_in[5];
    const float* Wo    = (const float*)d_in[6];
    const float* bo    = (const float*)d_in[7];
    const float* gamma = (const float*)d_in[8];
    const float* beta  = (const float*)d_in[9];
    const float* Wc    = (const float*)d_in[10];
    const float* bc    = (const float*)d_in[11];
    const float* Wr    = (const float*)d_in[12];
    const float* br    = (const float*)d_in[13];

    float* out    = (float*)d_out;
    float* logits = out;
    float* recon  = out + (size_t)ROWS * VOCAB;
    float* finals = recon + (size_t)ROWS * DD;

    float *h_p = nullptr, *h2_p = nullptr, *hn_p = nullptr;
    float *states_p = nullptr, *wcat_p = nullptr, *bcat_p = nullptr;
    float *wfold_p = nullptr, *bfold_p = nullptr, *sg_p = nullptr;
    cudaGetSymbolAddress((void**)&h_p,      g_h);
    cudaGetSymbolAddress((void**)&h2_p,     g_h2);
    cudaGetSymbolAddress((void**)&hn_p,     g_hn);
    cudaGetSymbolAddress((void**)&states_p, g_states);
    cudaGetSymbolAddress((void**)&wcat_p,   g_wcat);
    cudaGetSymbolAddress((void**)&bcat_p,   g_bcat);
    cudaGetSymbolAddress((void**)&wfold_p,  g_wfold);
    cudaGetSymbolAddress((void**)&bfold_p,  g_bfold);
    cudaGetSymbolAddress((void**)&sg_p,     g_sg);

    cudaFuncSetAttribute(logits_mma_kernel,
                         cudaFuncAttributeMaxDynamicSharedMemorySize, SMEM_BYTES);

    // ---- inputs / precompute ----
    embed_kernel<<<ROWS, DD>>>(x_t, table);
    convert_wc_kernel<<<(DD * VOCAB) / 1024, 256>>>(Wc);
    wf_kernel<<<DEPTH, DD>>>(Wi, bi, Wg, bg);
    // Wcat rows 0..255 = Wi1 @ Wo1, z-batched through the 128x64 engine
    gemm128_kernel<false, false><<<dim3(DD / 64, DD / 128, DEPTH), 256>>>(
        Wi, EE, (size_t)DD * EE, nullptr,
        Wo, DD, (size_t)EE * DD, nullptr,
        nullptr, nullptr,
        wcat_p, DD, (size_t)EE * DD, nullptr, DD);
    wcat_tail_kernel<<<DEPTH, DD>>>(Wo, bi, bo);            // rows 256..263 + bcat
    wfold_kernel<<<dim3(EE + 1, DEPTH - 1), 256>>>();       // F_i, bf_i (i=0..2)

    // ---- layers ----
    skinny_kernel<<<ROWS / 8, 256>>>(h_p, 0);               // sg_0 from embed h
    for (int i = 0; i < DEPTH; i++) {
        const float* hin  = (i & 1) ? h2_p : h_p;
        float*       hout = (i & 1) ? h_p  : h2_p;
        scan2_kernel<<<BB * SS, 256>>>(finals, i);
        if (i < DEPTH - 1) {
            gemm128_kernel<true, true><<<dim3(5, ROWS / 128), 256>>>(
                hin, DD, 0, states_p,
                wcat_p + (size_t)i * EE * DD, DD, 0,
                wfold_p + (size_t)i * EE * 16,
                bcat_p + (size_t)i * DD,
                bfold_p + (size_t)i * 16,
                hout, DD, 0, sg_p, EE);
        } else {
            gemm128_kernel<true, false><<<dim3(4, ROWS / 128), 256>>>(
                hin, DD, 0, states_p,
                wcat_p + (size_t)i * EE * DD, DD, 0,
                nullptr,
                bcat_p + (size_t)i * DD,
                nullptr,
                hout, DD, 0, nullptr, EE);
        }
    }

    ln_kernel<<<ROWS, DD>>>(gamma, beta);

    // logits via fp16 mma.sync
    logits_mma_kernel<<<dim3(VOCAB / GM_N, ROWS / GM_M), 256, SMEM_BYTES>>>(bc, logits);

    // recon = hn @ Wr + br (fp32)
    gemm128_kernel<false, false><<<dim3(4, ROWS / 128), 256>>>(
        hn_p, DD, 0, nullptr, Wr, DD, 0, nullptr, br, nullptr, recon, DD, 0, nullptr, DD);
}